// round 12
// baseline (speedup 1.0000x reference)
#include <cuda_runtime.h>
#include <cuda_bf16.h>
#include <cuda_fp16.h>
#include <math.h>
#include <stdint.h>

#define Bn 4
#define Cn 128
#define Hn 128
#define Wn 128
#define On 128
#define Kn 9
#define KKn 1152          // Cn * Kn   (main GEMM K)
#define OKK 2304          // offset conv K: 256 ch * 9, kk = c*9+k

// scratch: sampling coordinates + modulation mask, [B][K][H][W]
__device__ float g_py[Bn * Kn * Hn * Wn];
__device__ float g_px[Bn * Kn * Hn * Wn];
__device__ float g_m [Bn * Kn * Hn * Wn];
// pre-split main weights, fp16 hi/lo, [O][KK]
__device__ __half g_whi[On * KKn];
__device__ __half g_wlo[On * KKn];
// pre-split offset-conv weights, fp16 hi/lo, [32][OKK] (rows 27-31 zero)
__device__ __half g_owhi[32 * OKK];
__device__ __half g_owlo[32 * OKK];

#define SWZ(o) ((o) ^ (((o) >> 3) & 0x70))

__device__ __forceinline__ uint32_t smem_u32(const void* p) {
    uint32_t a;
    asm("{ .reg .u64 t; cvta.to.shared.u64 t, %1; cvt.u32.u64 %0, t; }"
        : "=r"(a) : "l"(p));
    return a;
}
__device__ __forceinline__ void ldsm4(uint32_t* r, uint32_t addr) {
    asm volatile("ldmatrix.sync.aligned.m8n8.x4.shared.b16 {%0,%1,%2,%3}, [%4];"
        : "=r"(r[0]), "=r"(r[1]), "=r"(r[2]), "=r"(r[3]) : "r"(addr));
}
__device__ __forceinline__ void mma_f16(float* d, const uint32_t* a,
                                        uint32_t b0, uint32_t b1) {
    asm volatile(
        "mma.sync.aligned.m16n8k16.row.col.f32.f16.f16.f32 "
        "{%0,%1,%2,%3}, {%4,%5,%6,%7}, {%8,%9}, {%0,%1,%2,%3};"
        : "+f"(d[0]), "+f"(d[1]), "+f"(d[2]), "+f"(d[3])
        : "r"(a[0]), "r"(a[1]), "r"(a[2]), "r"(a[3]), "r"(b0), "r"(b1));
}
__device__ __forceinline__ void cp16(uint32_t dst, const void* src) {
    asm volatile("cp.async.cg.shared.global [%0], [%1], 16;"
                 :: "r"(dst), "l"(src) : "memory");
}
#define CP_COMMIT() asm volatile("cp.async.commit_group;" ::: "memory")
#define CP_WAIT0()  asm volatile("cp.async.wait_group 0;" ::: "memory")
#define BAR_SYNC(id)   asm volatile("bar.sync %0, 512;"   :: "r"(id) : "memory")
#define BAR_ARRIVE(id) asm volatile("bar.arrive %0, 512;" :: "r"(id) : "memory")
#define MEMBAR_CTA()   asm volatile("membar.cta;" ::: "memory")

// packed fp16 pair
__device__ __forceinline__ uint32_t packh2(float v0, float v1) {
    uint32_t r;
    asm("cvt.rn.f16x2.f32 %0, %1, %2;" : "=r"(r) : "f"(v1), "f"(v0));
    return r;
}

// ---------------------------------------------------------------------------
// Kernel 0a/0b: weight splits (fp16 hi/lo)
// ---------------------------------------------------------------------------
__global__ void dcn_wsplit_kernel(const float* __restrict__ wgt) {
    int i = blockIdx.x * 256 + threadIdx.x;
    if (i < On * KKn) {
        float w = wgt[i];
        __half h = __float2half(w);
        g_whi[i] = h;
        g_wlo[i] = __float2half(w - __half2float(h));
    }
}
__global__ void dcn_owsplit_kernel(const float* __restrict__ offw) {
    int i = blockIdx.x * 256 + threadIdx.x;
    if (i >= 32 * OKK) return;
    int r = i / OKK;
    float w = (r < 27) ? offw[i] : 0.f;
    __half h = __float2half(w);
    g_owhi[i] = h;
    g_owlo[i] = __float2half(w - __half2float(h));
}

// ---------------------------------------------------------------------------
// Kernel 1: offset conv, warp-specialized fp16 2-term. One CTA per (b,y),
// grid 512 (no wave-quantization trap). 512 thr: warps 0-7 consumers
// (D = 32o x 128px, warp tile 16o x 32px), warps 8-15 producers (window
// reads -> fp16 B tile; A hi/lo via cp.async).
// per buffer (stride 24576): Ah +0 (4K), Al +4096 (4K), Bh +8192 (16K)
// ---------------------------------------------------------------------------
__global__ __launch_bounds__(512) void dcn_offset_mma(
    const float* __restrict__ inp,
    const float* __restrict__ inter,
    const float* __restrict__ offb)
{
    extern __shared__ char smem_raw[];
    char* tiles = (char*)(((uintptr_t)smem_raw + 1023) & ~(uintptr_t)1023);

    const int tid = threadIdx.x;
    const int wid = tid >> 5;
    const int lid = tid & 31;
    const int y   = blockIdx.x;
    const int b   = blockIdx.y;
    const uint32_t tbase = smem_u32(tiles);

    auto bload = [&](int chunk, int jg, int px0, float* fv) {
        #pragma unroll
        for (int j = 0; j < 8; ++j) {
            int kk = chunk * 64 + jg * 8 + j;
            int c  = kk / 9;
            int k  = kk - c * 9;
            int ky = k / 3;
            int kx = k - ky * 3;
            int yg = y + ky - 1;
            int xg = px0 + kx - 1;
            float v = 0.f;
            if (yg >= 0 && yg < Hn && xg >= 0 && xg < Wn) {
                const float* base = (c < Cn)
                    ? inp   + ((size_t)b * Cn + c) * (Hn * Wn)
                    : inter + ((size_t)b * Cn + (c - Cn)) * (Hn * Wn);
                v = base[yg * Wn + xg];
            }
            fv[j] = v;
        }
    };
    auto bstore = [&](char* bbuf, int jg, int px0, const float* fv) {
        uint4 vh4;
        vh4.x = packh2(fv[0], fv[1]);
        vh4.y = packh2(fv[2], fv[3]);
        vh4.z = packh2(fv[4], fv[5]);
        vh4.w = packh2(fv[6], fv[7]);
        uint32_t off = (uint32_t)(px0 * 128 + jg * 16);
        *(uint4*)(bbuf + 8192 + SWZ(off)) = vh4;
    };

    // prologue: all 512 threads fill buffer 0
    {
        char* buf = tiles;
        // A: 32 rows x 128B x 2 (hi/lo) = 512 uint4; 1 per thread
        {
            int i = tid;
            if (i < 512) {
                int tt  = i >> 8;
                int rem = i & 255;
                int r   = rem >> 3;
                int j   = rem & 7;
                const char* src = (tt ? (const char*)g_owlo : (const char*)g_owhi)
                                  + r * (OKK * 2) + j * 16;
                *(uint4*)(buf + tt * 4096 + SWZ((uint32_t)(r * 128 + j * 16)))
                    = *(const uint4*)src;
            }
        }
        // B: 8192 values / 512 thr = 2 items
        int px0 = tid & 127;
        int jb2 = (tid >> 7) * 2;
        float fv[8];
        #pragma unroll
        for (int it = 0; it < 2; ++it) {
            bload(0, jb2 + it, px0, fv);
            bstore(buf, jb2 + it, px0, fv);
        }
    }
    __syncthreads();

    if (wid < 8) {
        // ===================== CONSUMER =====================
        const int g  = lid >> 2;
        const int t  = lid & 3;
        const int m0 = (wid & 1) * 16;
        const int n0 = (wid >> 1) * 32;
        const int idx = lid >> 3, lr = lid & 7;
        const uint32_t aoff = (uint32_t)((m0 + (idx & 1) * 8 + lr) * 128 + (idx >> 1) * 16);
        uint32_t boffq[2];
        #pragma unroll
        for (int q = 0; q < 2; ++q)
            boffq[q] = (uint32_t)((n0 + q * 16 + (idx >> 1) * 8 + lr) * 128 + (idx & 1) * 16);

        float acc[4][4];
        #pragma unroll
        for (int j = 0; j < 4; j++)
            #pragma unroll
            for (int q = 0; q < 4; q++) acc[j][q] = 0.f;

        for (int c = 0; c < 36; ++c) {
            int s = c & 1;
            if (c) BAR_SYNC(1 + s);
            uint32_t bufb = tbase + (uint32_t)(s * 24576);
            uint32_t Ah = bufb, Al = bufb + 4096, Bh = bufb + 8192;
            #pragma unroll
            for (int ks = 0; ks < 4; ++ks) {
                uint32_t ah[4], al[4];
                uint32_t a0 = SWZ(aoff + ks * 32);
                ldsm4(ah, Ah + a0);
                ldsm4(al, Al + a0);
                #pragma unroll
                for (int q = 0; q < 2; ++q) {
                    uint32_t bo = SWZ(boffq[q] + ks * 32);
                    uint32_t bh[4];
                    ldsm4(bh, Bh + bo);
                    #pragma unroll
                    for (int hf = 0; hf < 2; ++hf) {
                        int nt = q * 2 + hf;
                        mma_f16(acc[nt], ah, bh[2*hf], bh[2*hf+1]);
                        mma_f16(acc[nt], al, bh[2*hf], bh[2*hf+1]);
                    }
                }
            }
            BAR_ARRIVE(3 + s);
        }

        // joint sync, then write D (+bias) to smem for the transform
        __syncthreads();
        float* Dsm = (float*)tiles;          // [32][132]
        {
            int r0 = m0 + g;
            int r1 = r0 + 8;
            float bo0 = (r0 < 27) ? offb[r0] : 0.f;
            float bo1 = (r1 < 27) ? offb[r1] : 0.f;
            #pragma unroll
            for (int nt = 0; nt < 4; ++nt) {
                int cx = n0 + nt * 8 + 2 * t;
                Dsm[r0 * 132 + cx]     = acc[nt][0] + bo0;
                Dsm[r0 * 132 + cx + 1] = acc[nt][1] + bo0;
                Dsm[r1 * 132 + cx]     = acc[nt][2] + bo1;
                Dsm[r1 * 132 + cx + 1] = acc[nt][3] + bo1;
            }
        }
    } else {
        // ===================== PRODUCER =====================
        const int ptid = tid - 256;
        const int px0  = ptid & 127;
        const int jb   = (ptid >> 7) * 4;
        for (int cn = 1; cn < 36; ++cn) {
            int s = cn & 1;
            if (cn >= 2) BAR_SYNC(3 + s);
            char* buf = tiles + (size_t)s * 24576;
            // A via cp.async: 2 x 16B per thread
            #pragma unroll
            for (int i = ptid; i < 512; i += 256) {
                int tt  = i >> 8;
                int rem = i & 255;
                int r   = rem >> 3;
                int j   = rem & 7;
                const char* src = (tt ? (const char*)g_owlo : (const char*)g_owhi)
                                  + r * (OKK * 2) + cn * 128 + j * 16;
                cp16(smem_u32(buf) + tt * 4096 + SWZ((uint32_t)(r * 128 + j * 16)), src);
            }
            CP_COMMIT();
            // B: 4 items, 2-deep pipelined window reads
            float fv[2][8];
            bload(cn, jb, px0, fv[0]);
            #pragma unroll
            for (int it = 0; it < 4; ++it) {
                if (it < 3) bload(cn, jb + it + 1, px0, fv[(it + 1) & 1]);
                bstore(buf, jb + it, px0, fv[it & 1]);
            }
            CP_WAIT0();
            MEMBAR_CTA();
            BAR_ARRIVE(1 + s);
        }
        __syncthreads();   // join for epilogue
    }

    __syncthreads();       // D ready
    // coordinate / mask transform
    if (tid < 128) {
        float* Dsm = (float*)tiles;
        int x = tid;
        #pragma unroll
        for (int k = 0; k < 9; ++k) {
            float dy = Dsm[(2 * k) * 132 + x];
            float dx = Dsm[(2 * k + 1) * 132 + x];
            float mv = 1.f / (1.f + expf(-Dsm[(18 + k) * 132 + x]));
            int idx2 = ((b * Kn + k) * Hn + y) * Wn + x;
            g_py[idx2] = dy + (float)(y - 1 + (k / 3));
            g_px[idx2] = dx + (float)(x - 1 + (k % 3));
            g_m [idx2] = mv;
        }
    }
}

// ---------------------------------------------------------------------------
// Kernel 2 (unchanged R11): main GEMM, warp-specialized, fp16 2-term.
// per buffer (stride 49152): Ah +0 (16K), Al +16384, Bh +32768. tables @98304.
// ---------------------------------------------------------------------------
__global__ __launch_bounds__(512) void dcn_main_mma(
    const float* __restrict__ inp,
    const float* __restrict__ bias,
    float* __restrict__ out)
{
    extern __shared__ char smem_raw[];
    char* tiles = (char*)(((uintptr_t)smem_raw + 1023) & ~(uintptr_t)1023);
    float4*   cwgt = (float4*)(tiles + 98304);            // [9*128]
    uint32_t* cpak = (uint32_t*)(tiles + 98304 + 18432);  // [9*128]

    const int tid = threadIdx.x;
    const int wid = tid >> 5;
    const int lid = tid & 31;
    const int y   = blockIdx.x;
    const int b   = blockIdx.y;
    const uint32_t tbase = smem_u32(tiles);
    const float* binp = inp + (size_t)b * Cn * Hn * Wn;

    // corner tables (all 512 threads)
    for (int e = tid; e < 1152; e += 512) {
        int k  = e >> 7;
        int px = e & 127;
        int gi = ((b * Kn + k) * Hn + y) * Wn + px;
        float pyv = g_py[gi];
        float pxv = g_px[gi];
        float mv  = g_m[gi];
        float y0f = floorf(pyv);
        float x0f = floorf(pxv);
        float wy = pyv - y0f;
        float wx = pxv - x0f;
        int yI = (int)y0f;
        int xI = (int)x0f;
        float vy0 = (yI >= 0  && yI <= Hn - 1) ? 1.f : 0.f;
        float vy1 = (yI >= -1 && yI <= Hn - 2) ? 1.f : 0.f;
        float vx0 = (xI >= 0  && xI <= Wn - 1) ? 1.f : 0.f;
        float vx1 = (xI >= -1 && xI <= Wn - 2) ? 1.f : 0.f;
        float w00 = (1.f - wy) * (1.f - wx) * mv * (vy0 * vx0);
        float w01 = (1.f - wy) * wx         * mv * (vy0 * vx1);
        float w10 = wy * (1.f - wx)         * mv * (vy1 * vx0);
        float w11 = wy * wx                 * mv * (vy1 * vx1);
        int y0c = min(max(yI, 0), Hn - 1);
        int y1c = min(max(yI + 1, 0), Hn - 1);
        int x0c = min(max(xI, 0), Wn - 1);
        int x1c = min(max(xI + 1, 0), Wn - 1);
        cwgt[e] = make_float4(w00, w01, w10, w11);
        cpak[e] = (uint32_t)(y0c * Wn + x0c)
                | ((uint32_t)(x1c - x0c) << 14)
                | ((uint32_t)(y1c - y0c) << 15);
    }
    __syncthreads();

    auto bload = [&](int chunk, int jg, int px0, float* cr) {
        #pragma unroll
        for (int j = 0; j < 8; ++j) {
            int kk = chunk * 64 + jg * 8 + j;
            int c9 = kk / 9;
            int k  = kk - c9 * 9;
            int e  = (k << 7) + px0;
            uint32_t p = cpak[e];
            int base = (int)(p & 0x3fff);
            int dxs  = (int)((p >> 14) & 1);
            int dyr  = ((int)((p >> 15) & 1)) << 7;
            const float* pl = binp + (c9 << 14);
            cr[4*j+0] = pl[base];
            cr[4*j+1] = pl[base + dxs];
            cr[4*j+2] = pl[base + dyr];
            cr[4*j+3] = pl[base + dyr + dxs];
        }
    };
    auto bstore = [&](char* bbuf, int chunk, int jg, int px0, const float* cr) {
        float v[8];
        #pragma unroll
        for (int j = 0; j < 8; ++j) {
            int kk = chunk * 64 + jg * 8 + j;
            int c9 = kk / 9;
            int k  = kk - c9 * 9;
            int e  = (k << 7) + px0;
            float4 w = cwgt[e];
            v[j] = w.x * cr[4*j+0] + w.y * cr[4*j+1]
                 + w.z * cr[4*j+2] + w.w * cr[4*j+3];
        }
        uint4 vh4;
        vh4.x = packh2(v[0], v[1]);
        vh4.y = packh2(v[2], v[3]);
        vh4.z = packh2(v[4], v[5]);
        vh4.w = packh2(v[6], v[7]);
        uint32_t off = (uint32_t)(px0 * 128 + jg * 16);
        *(uint4*)(bbuf + SWZ(off)) = vh4;
    };

    // prologue: all 512 threads fill buffer 0
    {
        char* A0 = tiles;
        char* B0 = tiles + 32768;
        #pragma unroll
        for (int i = tid; i < 2048; i += 512) {
            int tt = i >> 10;
            int r  = (i >> 3) & 127;
            int j  = i & 7;
            const char* src = (tt ? (const char*)g_wlo : (const char*)g_whi)
                              + r * 2304 + j * 16;
            *(uint4*)(A0 + tt * 16384 + SWZ((uint32_t)(r * 128 + j * 16)))
                = *(const uint4*)src;
        }
        int px0 = tid & 127;
        int jb  = (tid >> 7) * 2;
        float cr[32];
        #pragma unroll
        for (int it = 0; it < 2; ++it) {
            bload(0, jb + it, px0, cr);
            bstore(B0, 0, jb + it, px0, cr);
        }
    }
    __syncthreads();

    if (wid < 8) {
        // ===================== CONSUMER =====================
        const int g  = lid >> 2;
        const int t  = lid & 3;
        const int m0 = (wid & 3) * 32;
        const int n0 = (wid >> 2) * 64;
        const int idx = lid >> 3, lr = lid & 7;
        const uint32_t aoff0 = (uint32_t)((m0 + (idx & 1) * 8 + lr) * 128 + (idx >> 1) * 16);
        const uint32_t aoff1 = aoff0 + 16 * 128;
        uint32_t boffq[4];
        #pragma unroll
        for (int q = 0; q < 4; ++q)
            boffq[q] = (uint32_t)((n0 + q * 16 + (idx >> 1) * 8 + lr) * 128 + (idx & 1) * 16);

        float acc[2][8][4];
        #pragma unroll
        for (int i = 0; i < 2; i++)
            #pragma unroll
            for (int j = 0; j < 8; j++)
                #pragma unroll
                for (int q = 0; q < 4; q++) acc[i][j][q] = 0.f;

        for (int c = 0; c < 18; ++c) {
            int s = c & 1;
            if (c) BAR_SYNC(1 + s);
            uint32_t bufb = tbase + (uint32_t)(s * 49152);
            uint32_t Ah = bufb, Al = bufb + 16384, Bh = bufb + 32768;
            #pragma unroll
            for (int ks = 0; ks < 4; ++ks) {
                uint32_t ah[2][4], al[2][4];
                uint32_t a0 = SWZ(aoff0 + ks * 32);
                uint32_t a1 = SWZ(aoff1 + ks * 32);
                ldsm4(ah[0], Ah + a0); ldsm4(ah[1], Ah + a1);
                ldsm4(al[0], Al + a0); ldsm4(al[1], Al + a1);
                #pragma unroll
                for (int q = 0; q < 4; ++q) {
                    uint32_t bo = SWZ(boffq[q] + ks * 32);
                    uint32_t bh[4];
                    ldsm4(bh, Bh + bo);
                    #pragma unroll
                    for (int hf = 0; hf < 2; ++hf) {
                        int nt = q * 2 + hf;
                        uint32_t h0 = bh[2*hf], h1 = bh[2*hf+1];
                        #pragma unroll
                        for (int mt = 0; mt < 2; ++mt) {
                            mma_f16(acc[mt][nt], ah[mt], h0, h1);
                            mma_f16(acc[mt][nt], al[mt], h0, h1);
                        }
                    }
                }
            }
            BAR_ARRIVE(3 + s);
        }

        // epilogue: add bias, store float2 pairs
        #pragma unroll
        for (int mt = 0; mt < 2; ++mt) {
            int r0 = m0 + mt * 16 + g;
            int r1 = r0 + 8;
            float bo0 = bias[r0];
            float bo1 = bias[r1];
            float* row0 = out + (((size_t)b * On + r0) * Hn + y) * Wn;
            float* row1 = out + (((size_t)b * On + r1) * Hn + y) * Wn;
            #pragma unroll
            for (int nt = 0; nt < 8; ++nt) {
                int cx = n0 + nt * 8 + 2 * t;
                float2 v0 = make_float2(acc[mt][nt][0] + bo0, acc[mt][nt][1] + bo0);
                float2 v1 = make_float2(acc[mt][nt][2] + bo1, acc[mt][nt][3] + bo1);
                *(float2*)(row0 + cx) = v0;
                *(float2*)(row1 + cx) = v1;
            }
        }
    } else {
        // ===================== PRODUCER =====================
        const int ptid = tid - 256;
        const int px0  = ptid & 127;
        const int jb   = (ptid >> 7) * 4;
        for (int cn = 1; cn < 18; ++cn) {
            int s = cn & 1;
            if (cn >= 2) BAR_SYNC(3 + s);
            char* Abuf = tiles + (size_t)s * 49152;
            char* Bbuf = tiles + 32768 + (size_t)s * 49152;
            // A via cp.async: 8 x 16B per thread
            #pragma unroll
            for (int i = ptid; i < 2048; i += 256) {
                int tt = i >> 10;
                int r  = (i >> 3) & 127;
                int j  = i & 7;
                const char* src = (tt ? (const char*)g_wlo : (const char*)g_whi)
                                  + r * 2304 + cn * 128 + j * 16;
                cp16(smem_u32(Abuf) + tt * 16384 + SWZ((uint32_t)(r * 128 + j * 16)), src);
            }
            CP_COMMIT();
            // B: 4 items, 2-deep pipelined gather
            float cr[2][32];
            bload(cn, jb, px0, cr[0]);
            #pragma unroll
            for (int it = 0; it < 4; ++it) {
                if (it < 3) bload(cn, jb + it + 1, px0, cr[(it + 1) & 1]);
                bstore(Bbuf, cn, jb + it, px0, cr[it & 1]);
            }
            CP_WAIT0();
            MEMBAR_CTA();
            BAR_ARRIVE(1 + s);
        }
    }
}

// ---------------------------------------------------------------------------
extern "C" void kernel_launch(void* const* d_in, const int* in_sizes, int n_in,
                              void* d_out, int out_size)
{
    const float* inp   = (const float*)d_in[0];
    const float* inter = (const float*)d_in[1];
    const float* offw  = (const float*)d_in[2];
    const float* offb  = (const float*)d_in[3];
    const float* wgt   = (const float*)d_in[4];
    const float* bias  = (const float*)d_in[5];
    float* out = (float*)d_out;

    dcn_wsplit_kernel<<<(On * KKn + 255) / 256, 256>>>(wgt);
    dcn_owsplit_kernel<<<(32 * OKK + 255) / 256, 256>>>(offw);

    size_t smem1 = 1024 + 2 * 24576;   // 50,176 B
    cudaFuncSetAttribute(dcn_offset_mma,
                         cudaFuncAttributeMaxDynamicSharedMemorySize, (int)smem1);
    dcn_offset_mma<<<dim3(Hn, Bn), 512, smem1>>>(inp, inter, offb);

    size_t smem2 = 1024 + 2 * 49152 + 18432 + 4608;   // 122,368 B
    cudaFuncSetAttribute(dcn_main_mma,
                         cudaFuncAttributeMaxDynamicSharedMemorySize, (int)smem2);
    dcn_main_mma<<<dim3(Hn, Bn), 512, smem2>>>(inp, bias, out);
}

// round 13
// speedup vs baseline: 1.6266x; 1.6266x over previous
#include <cuda_runtime.h>
#include <cuda_bf16.h>
#include <cuda_fp16.h>
#include <math.h>
#include <stdint.h>

#define Bn 4
#define Cn 128
#define Hn 128
#define Wn 128
#define On 128
#define Kn 9
#define KKn 1152          // Cn * Kn   (main GEMM K)
#define OKK 2304          // offset conv K: 256 ch * 9, kk = c*9+k

// scratch: sampling coordinates + modulation mask, [B][K][H][W]
__device__ float g_py[Bn * Kn * Hn * Wn];
__device__ float g_px[Bn * Kn * Hn * Wn];
__device__ float g_m [Bn * Kn * Hn * Wn];
// main weights, single fp16, [O][KK]
__device__ __half g_whi[On * KKn];
// pre-split offset-conv weights, bf16 hi/lo, [32][OKK] (rows 27-31 zero)
__device__ __nv_bfloat16 g_owhi[32 * OKK];
__device__ __nv_bfloat16 g_owlo[32 * OKK];

#define SWZ(o) ((o) ^ (((o) >> 3) & 0x70))

__device__ __forceinline__ uint32_t smem_u32(const void* p) {
    uint32_t a;
    asm("{ .reg .u64 t; cvta.to.shared.u64 t, %1; cvt.u32.u64 %0, t; }"
        : "=r"(a) : "l"(p));
    return a;
}
__device__ __forceinline__ void ldsm4(uint32_t* r, uint32_t addr) {
    asm volatile("ldmatrix.sync.aligned.m8n8.x4.shared.b16 {%0,%1,%2,%3}, [%4];"
        : "=r"(r[0]), "=r"(r[1]), "=r"(r[2]), "=r"(r[3]) : "r"(addr));
}
// bf16 MMA (offset kernel)
__device__ __forceinline__ void mma_bf16(float* d, const uint32_t* a,
                                         uint32_t b0, uint32_t b1) {
    asm volatile(
        "mma.sync.aligned.m16n8k16.row.col.f32.bf16.bf16.f32 "
        "{%0,%1,%2,%3}, {%4,%5,%6,%7}, {%8,%9}, {%0,%1,%2,%3};"
        : "+f"(d[0]), "+f"(d[1]), "+f"(d[2]), "+f"(d[3])
        : "r"(a[0]), "r"(a[1]), "r"(a[2]), "r"(a[3]), "r"(b0), "r"(b1));
}
// fp16 MMA (main kernel)
__device__ __forceinline__ void mma_f16(float* d, const uint32_t* a,
                                        uint32_t b0, uint32_t b1) {
    asm volatile(
        "mma.sync.aligned.m16n8k16.row.col.f32.f16.f16.f32 "
        "{%0,%1,%2,%3}, {%4,%5,%6,%7}, {%8,%9}, {%0,%1,%2,%3};"
        : "+f"(d[0]), "+f"(d[1]), "+f"(d[2]), "+f"(d[3])
        : "r"(a[0]), "r"(a[1]), "r"(a[2]), "r"(a[3]), "r"(b0), "r"(b1));
}
__device__ __forceinline__ void cp16(uint32_t dst, const void* src) {
    asm volatile("cp.async.cg.shared.global [%0], [%1], 16;"
                 :: "r"(dst), "l"(src) : "memory");
}
#define CP_COMMIT() asm volatile("cp.async.commit_group;" ::: "memory")
#define CP_WAIT0()  asm volatile("cp.async.wait_group 0;" ::: "memory")
#define BAR_SYNC(id)   asm volatile("bar.sync %0, 512;"   :: "r"(id) : "memory")
#define BAR_ARRIVE(id) asm volatile("bar.arrive %0, 512;" :: "r"(id) : "memory")
#define MEMBAR_CTA()   asm volatile("membar.cta;" ::: "memory")

// packed bf16 split: lower bf16 = v0, upper = v1; lo2 = residuals
__device__ __forceinline__ void split2(float v0, float v1,
                                       uint32_t& hi2, uint32_t& lo2) {
    uint32_t h;
    asm("cvt.rn.bf16x2.f32 %0, %1, %2;" : "=r"(h) : "f"(v1), "f"(v0));
    float h0 = __uint_as_float(h << 16);
    float h1 = __uint_as_float(h & 0xffff0000u);
    asm("cvt.rn.bf16x2.f32 %0, %1, %2;"
        : "=r"(lo2) : "f"(v1 - h1), "f"(v0 - h0));
    hi2 = h;
}
// packed fp16 pair
__device__ __forceinline__ uint32_t packh2(float v0, float v1) {
    uint32_t r;
    asm("cvt.rn.f16x2.f32 %0, %1, %2;" : "=r"(r) : "f"(v1), "f"(v0));
    return r;
}

// ---------------------------------------------------------------------------
// Kernel 0a/0b: weight prep
// ---------------------------------------------------------------------------
__global__ void dcn_wsplit_kernel(const float* __restrict__ wgt) {
    int i = blockIdx.x * 256 + threadIdx.x;
    if (i < On * KKn) g_whi[i] = __float2half(wgt[i]);
}
__global__ void dcn_owsplit_kernel(const float* __restrict__ offw) {
    int i = blockIdx.x * 256 + threadIdx.x;
    if (i >= 32 * OKK) return;
    int r = i / OKK;
    float w = (r < 27) ? offw[i] : 0.f;
    __nv_bfloat16 h = __float2bfloat16(w);
    g_owhi[i] = h;
    g_owlo[i] = __float2bfloat16(w - __bfloat162float(h));
}

// ---------------------------------------------------------------------------
// Kernel 1 (R10 structure, measured best): offset conv via HMMA bf16 3-term,
// interleaved fill + MMA, one CTA per (b,y): 512 thr, warp tile 16o x 16px.
// per buffer (stride 40960): Ah +0, Al +4096, Bh +8192, Bl +24576
// ---------------------------------------------------------------------------
__global__ __launch_bounds__(512) void dcn_offset_mma(
    const float* __restrict__ inp,
    const float* __restrict__ inter,
    const float* __restrict__ offb)
{
    extern __shared__ char smem_raw[];
    char* tiles = (char*)(((uintptr_t)smem_raw + 1023) & ~(uintptr_t)1023);

    const int tid = threadIdx.x;
    const int wid = tid >> 5;
    const int lid = tid & 31;
    const int g   = lid >> 2;
    const int t   = lid & 3;
    const int y   = blockIdx.x;
    const int b   = blockIdx.y;
    const int m0  = (wid & 1) * 16;
    const int n0  = (wid >> 1) * 16;

    const int idx = lid >> 3, lr = lid & 7;
    const uint32_t aoffb = (uint32_t)((m0 + (idx & 1) * 8 + lr) * 128 + (idx >> 1) * 16);
    const uint32_t boffb = (uint32_t)((n0 + (idx >> 1) * 8 + lr) * 128 + (idx & 1) * 16);
    const uint32_t tbase = smem_u32(tiles);

    const int px0 = tid & 127;
    const int jg0 = tid >> 7;

    float acc[2][4];
    #pragma unroll
    for (int j = 0; j < 2; j++)
        #pragma unroll
        for (int q = 0; q < 4; q++) acc[j][q] = 0.f;

    auto bload = [&](int chunk, int jg, float* fv) {
        #pragma unroll
        for (int j = 0; j < 8; ++j) {
            int kk = chunk * 64 + jg * 8 + j;
            int c  = kk / 9;
            int k  = kk - c * 9;
            int ky = k / 3;
            int kx = k - ky * 3;
            int yg = y + ky - 1;
            int xg = px0 + kx - 1;
            float v = 0.f;
            if (yg >= 0 && yg < Hn && xg >= 0 && xg < Wn) {
                const float* base = (c < Cn)
                    ? inp   + ((size_t)b * Cn + c) * (Hn * Wn)
                    : inter + ((size_t)b * Cn + (c - Cn)) * (Hn * Wn);
                v = base[yg * Wn + xg];
            }
            fv[j] = v;
        }
    };
    auto bstore = [&](char* buf, int jg, const float* fv) {
        uint4 vh4, vl4;
        split2(fv[0], fv[1], vh4.x, vl4.x);
        split2(fv[2], fv[3], vh4.y, vl4.y);
        split2(fv[4], fv[5], vh4.z, vl4.z);
        split2(fv[6], fv[7], vh4.w, vl4.w);
        uint32_t off = (uint32_t)(px0 * 128 + jg * 16);
        *(uint4*)(buf + 8192  + SWZ(off)) = vh4;
        *(uint4*)(buf + 24576 + SWZ(off)) = vl4;
    };
    auto mma_half = [&](uint32_t cu, int ks0) {
        uint32_t Ah = cu, Al = cu + 4096, Bh = cu + 8192, Bl = cu + 24576;
        #pragma unroll
        for (int kq = 0; kq < 2; ++kq) {
            int ks = ks0 + kq;
            uint32_t ah[4], al[4], bh[4], bl[4];
            uint32_t ao = SWZ(aoffb + ks * 32);
            uint32_t bo = SWZ(boffb + ks * 32);
            ldsm4(ah, Ah + ao);
            ldsm4(al, Al + ao);
            ldsm4(bh, Bh + bo);
            ldsm4(bl, Bl + bo);
            #pragma unroll
            for (int nt = 0; nt < 2; ++nt) {
                mma_bf16(acc[nt], ah, bh[2*nt], bh[2*nt+1]);
                mma_bf16(acc[nt], ah, bl[2*nt], bl[2*nt+1]);
                mma_bf16(acc[nt], al, bh[2*nt], bh[2*nt+1]);
            }
        }
    };

    // prologue: synchronous fill of chunk 0
    {
        char* buf = tiles;
        {
            int i = tid;
            if (i < 512) {
                int tt = i >> 8;
                int r  = (i >> 3) & 31;
                int j  = i & 7;
                const char* src = (tt ? (const char*)g_owlo : (const char*)g_owhi)
                                  + r * (OKK * 2) + j * 16;
                *(uint4*)(buf + tt * 4096 + SWZ((uint32_t)(r * 128 + j * 16)))
                    = *(const uint4*)src;
            }
        }
        float fv[8];
        bload(0, jg0, fv);     bstore(buf, jg0, fv);
        bload(0, jg0 + 4, fv); bstore(buf, jg0 + 4, fv);
    }
    __syncthreads();

    for (int c = 0; c < 36; ++c) {
        uint32_t cu = tbase + (uint32_t)((c & 1) * 40960);
        char* nbuf  = tiles + (size_t)((c + 1) & 1) * 40960;
        uint32_t nb = tbase + (uint32_t)(((c + 1) & 1) * 40960);
        const bool pre = (c + 1 < 36);

        if (pre) {
            int i  = tid;
            int tt = i >> 8;
            int r  = (i >> 3) & 31;
            int j  = i & 7;
            const char* src = (tt ? (const char*)g_owlo : (const char*)g_owhi)
                              + r * (OKK * 2) + (c + 1) * 128 + j * 16;
            cp16(nb + tt * 4096 + SWZ((uint32_t)(r * 128 + j * 16)), src);
            CP_COMMIT();
        }

        float fv[8];
        if (pre) bload(c + 1, jg0, fv);
        mma_half(cu, 0);
        if (pre) bstore(nbuf, jg0, fv);

        if (pre) bload(c + 1, jg0 + 4, fv);
        mma_half(cu, 2);
        if (pre) bstore(nbuf, jg0 + 4, fv);

        if (pre) CP_WAIT0();
        __syncthreads();
    }

    // epilogue 1: fragments -> smem D[32][132] (+ bias)
    float* Dsm = (float*)tiles;
    {
        int r0 = m0 + g;
        int r1 = r0 + 8;
        float bo0 = (r0 < 27) ? offb[r0] : 0.f;
        float bo1 = (r1 < 27) ? offb[r1] : 0.f;
        #pragma unroll
        for (int nt = 0; nt < 2; ++nt) {
            int cx = n0 + nt * 8 + 2 * t;
            Dsm[r0 * 132 + cx]     = acc[nt][0] + bo0;
            Dsm[r0 * 132 + cx + 1] = acc[nt][1] + bo0;
            Dsm[r1 * 132 + cx]     = acc[nt][2] + bo1;
            Dsm[r1 * 132 + cx + 1] = acc[nt][3] + bo1;
        }
    }
    __syncthreads();

    // epilogue 2: coordinate / mask transform
    if (tid < 128) {
        int x = tid;
        #pragma unroll
        for (int k = 0; k < 9; ++k) {
            float dy = Dsm[(2 * k) * 132 + x];
            float dx = Dsm[(2 * k + 1) * 132 + x];
            float mv = 1.f / (1.f + expf(-Dsm[(18 + k) * 132 + x]));
            int idx2 = ((b * Kn + k) * Hn + y) * Wn + x;
            g_py[idx2] = dy + (float)(y - 1 + (k / 3));
            g_px[idx2] = dx + (float)(x - 1 + (k % 3));
            g_m [idx2] = mv;
        }
    }
}

// ---------------------------------------------------------------------------
// Kernel 2: main GEMM, warp-specialized, single-term fp16 (A plain fp16,
// B plain fp16). One CTA per (b,y): warps 0-7 consumers (tile 32o x 64px),
// warps 8-15 producers. per buffer (stride 32768): A +0 (16K), B +16384.
// tables @65536.
// ---------------------------------------------------------------------------
__global__ __launch_bounds__(512) void dcn_main_mma(
    const float* __restrict__ inp,
    const float* __restrict__ bias,
    float* __restrict__ out)
{
    extern __shared__ char smem_raw[];
    char* tiles = (char*)(((uintptr_t)smem_raw + 1023) & ~(uintptr_t)1023);
    float4*   cwgt = (float4*)(tiles + 65536);            // [9*128]
    uint32_t* cpak = (uint32_t*)(tiles + 65536 + 18432);  // [9*128]

    const int tid = threadIdx.x;
    const int wid = tid >> 5;
    const int lid = tid & 31;
    const int y   = blockIdx.x;
    const int b   = blockIdx.y;
    const uint32_t tbase = smem_u32(tiles);
    const float* binp = inp + (size_t)b * Cn * Hn * Wn;

    // corner tables (all 512 threads)
    for (int e = tid; e < 1152; e += 512) {
        int k  = e >> 7;
        int px = e & 127;
        int gi = ((b * Kn + k) * Hn + y) * Wn + px;
        float pyv = g_py[gi];
        float pxv = g_px[gi];
        float mv  = g_m[gi];
        float y0f = floorf(pyv);
        float x0f = floorf(pxv);
        float wy = pyv - y0f;
        float wx = pxv - x0f;
        int yI = (int)y0f;
        int xI = (int)x0f;
        float vy0 = (yI >= 0  && yI <= Hn - 1) ? 1.f : 0.f;
        float vy1 = (yI >= -1 && yI <= Hn - 2) ? 1.f : 0.f;
        float vx0 = (xI >= 0  && xI <= Wn - 1) ? 1.f : 0.f;
        float vx1 = (xI >= -1 && xI <= Wn - 2) ? 1.f : 0.f;
        float w00 = (1.f - wy) * (1.f - wx) * mv * (vy0 * vx0);
        float w01 = (1.f - wy) * wx         * mv * (vy0 * vx1);
        float w10 = wy * (1.f - wx)         * mv * (vy1 * vx0);
        float w11 = wy * wx                 * mv * (vy1 * vx1);
        int y0c = min(max(yI, 0), Hn - 1);
        int y1c = min(max(yI + 1, 0), Hn - 1);
        int x0c = min(max(xI, 0), Wn - 1);
        int x1c = min(max(xI + 1, 0), Wn - 1);
        cwgt[e] = make_float4(w00, w01, w10, w11);
        cpak[e] = (uint32_t)(y0c * Wn + x0c)
                | ((uint32_t)(x1c - x0c) << 14)
                | ((uint32_t)(y1c - y0c) << 15);
    }
    __syncthreads();

    auto bload = [&](int chunk, int jg, int px0, float* cr) {
        #pragma unroll
        for (int j = 0; j < 8; ++j) {
            int kk = chunk * 64 + jg * 8 + j;
            int c9 = kk / 9;
            int k  = kk - c9 * 9;
            int e  = (k << 7) + px0;
            uint32_t p = cpak[e];
            int base = (int)(p & 0x3fff);
            int dxs  = (int)((p >> 14) & 1);
            int dyr  = ((int)((p >> 15) & 1)) << 7;
            const float* pl = binp + (c9 << 14);
            cr[4*j+0] = pl[base];
            cr[4*j+1] = pl[base + dxs];
            cr[4*j+2] = pl[base + dyr];
            cr[4*j+3] = pl[base + dyr + dxs];
        }
    };
    auto bstore = [&](char* bbuf, int chunk, int jg, int px0, const float* cr) {
        float v[8];
        #pragma unroll
        for (int j = 0; j < 8; ++j) {
            int kk = chunk * 64 + jg * 8 + j;
            int c9 = kk / 9;
            int k  = kk - c9 * 9;
            int e  = (k << 7) + px0;
            float4 w = cwgt[e];
            v[j] = w.x * cr[4*j+0] + w.y * cr[4*j+1]
                 + w.z * cr[4*j+2] + w.w * cr[4*j+3];
        }
        uint4 vh4;
        vh4.x = packh2(v[0], v[1]);
        vh4.y = packh2(v[2], v[3]);
        vh4.z = packh2(v[4], v[5]);
        vh4.w = packh2(v[6], v[7]);
        uint32_t off = (uint32_t)(px0 * 128 + jg * 16);
        *(uint4*)(bbuf + SWZ(off)) = vh4;
    };

    // prologue: all 512 threads fill buffer 0
    {
        char* A0 = tiles;
        char* B0 = tiles + 16384;
        #pragma unroll
        for (int i = tid; i < 1024; i += 512) {
            int r = i >> 3;
            int j = i & 7;
            const char* src = (const char*)g_whi + r * 2304 + j * 16;
            *(uint4*)(A0 + SWZ((uint32_t)(r * 128 + j * 16))) = *(const uint4*)src;
        }
        int px0 = tid & 127;
        int jb  = (tid >> 7) * 2;
        float cr[32];
        #pragma unroll
        for (int it = 0; it < 2; ++it) {
            bload(0, jb + it, px0, cr);
            bstore(B0, 0, jb + it, px0, cr);
        }
    }
    __syncthreads();

    if (wid < 8) {
        // ===================== CONSUMER =====================
        const int g  = lid >> 2;
        const int t  = lid & 3;
        const int m0 = (wid & 3) * 32;
        const int n0 = (wid >> 2) * 64;
        const int idx = lid >> 3, lr = lid & 7;
        const uint32_t aoff0 = (uint32_t)((m0 + (idx & 1) * 8 + lr) * 128 + (idx >> 1) * 16);
        const uint32_t aoff1 = aoff0 + 16 * 128;
        uint32_t boffq[4];
        #pragma unroll
        for (int q = 0; q < 4; ++q)
            boffq[q] = (uint32_t)((n0 + q * 16 + (idx >> 1) * 8 + lr) * 128 + (idx & 1) * 16);

        float acc[2][8][4];
        #pragma unroll
        for (int i = 0; i < 2; i++)
            #pragma unroll
            for (int j = 0; j < 8; j++)
                #pragma unroll
                for (int q = 0; q < 4; q++) acc[i][j][q] = 0.f;

        for (int c = 0; c < 18; ++c) {
            int s = c & 1;
            if (c) BAR_SYNC(1 + s);
            uint32_t bufb = tbase + (uint32_t)(s * 32768);
            uint32_t Ah = bufb, Bh = bufb + 16384;
            #pragma unroll
            for (int ks = 0; ks < 4; ++ks) {
                uint32_t ah[2][4];
                uint32_t a0 = SWZ(aoff0 + ks * 32);
                uint32_t a1 = SWZ(aoff1 + ks * 32);
                ldsm4(ah[0], Ah + a0); ldsm4(ah[1], Ah + a1);
                #pragma unroll
                for (int q = 0; q < 4; ++q) {
                    uint32_t bo = SWZ(boffq[q] + ks * 32);
                    uint32_t bh[4];
                    ldsm4(bh, Bh + bo);
                    #pragma unroll
                    for (int hf = 0; hf < 2; ++hf) {
                        int nt = q * 2 + hf;
                        uint32_t h0 = bh[2*hf], h1 = bh[2*hf+1];
                        #pragma unroll
                        for (int mt = 0; mt < 2; ++mt)
                            mma_f16(acc[mt][nt], ah[mt], h0, h1);
                    }
                }
            }
            BAR_ARRIVE(3 + s);
        }

        // epilogue: add bias, store float2 pairs
        #pragma unroll
        for (int mt = 0; mt < 2; ++mt) {
            int r0 = m0 + mt * 16 + g;
            int r1 = r0 + 8;
            float bo0 = bias[r0];
            float bo1 = bias[r1];
            float* row0 = out + (((size_t)b * On + r0) * Hn + y) * Wn;
            float* row1 = out + (((size_t)b * On + r1) * Hn + y) * Wn;
            #pragma unroll
            for (int nt = 0; nt < 8; ++nt) {
                int cx = n0 + nt * 8 + 2 * t;
                float2 v0 = make_float2(acc[mt][nt][0] + bo0, acc[mt][nt][1] + bo0);
                float2 v1 = make_float2(acc[mt][nt][2] + bo1, acc[mt][nt][3] + bo1);
                *(float2*)(row0 + cx) = v0;
                *(float2*)(row1 + cx) = v1;
            }
        }
    } else {
        // ===================== PRODUCER =====================
        const int ptid = tid - 256;
        const int px0  = ptid & 127;
        const int jb   = (ptid >> 7) * 4;
        for (int cn = 1; cn < 18; ++cn) {
            int s = cn & 1;
            if (cn >= 2) BAR_SYNC(3 + s);
            char* Abuf = tiles + (size_t)s * 32768;
            char* Bbuf = tiles + 16384 + (size_t)s * 32768;
            // A via cp.async: 4 x 16B per thread
            #pragma unroll
            for (int i = ptid; i < 1024; i += 256) {
                int r = i >> 3;
                int j = i & 7;
                const char* src = (const char*)g_whi + r * 2304 + cn * 128 + j * 16;
                cp16(smem_u32(Abuf) + SWZ((uint32_t)(r * 128 + j * 16)), src);
            }
            CP_COMMIT();
            // B: 4 items, 2-deep pipelined gather
            float cr[2][32];
            bload(cn, jb, px0, cr[0]);
            #pragma unroll
            for (int it = 0; it < 4; ++it) {
                if (it < 3) bload(cn, jb + it + 1, px0, cr[(it + 1) & 1]);
                bstore(Bbuf, cn, jb + it, px0, cr[it & 1]);
            }
            CP_WAIT0();
            MEMBAR_CTA();
            BAR_ARRIVE(1 + s);
        }
    }
}

// ---------------------------------------------------------------------------
extern "C" void kernel_launch(void* const* d_in, const int* in_sizes, int n_in,
                              void* d_out, int out_size)
{
    const float* inp   = (const float*)d_in[0];
    const float* inter = (const float*)d_in[1];
    const float* offw  = (const float*)d_in[2];
    const float* offb  = (const float*)d_in[3];
    const float* wgt   = (const float*)d_in[4];
    const float* bias  = (const float*)d_in[5];
    float* out = (float*)d_out;

    dcn_wsplit_kernel<<<(On * KKn + 255) / 256, 256>>>(wgt);
    dcn_owsplit_kernel<<<(32 * OKK + 255) / 256, 256>>>(offw);

    size_t smem1 = 1024 + 2 * 40960;   // 82,944 B
    cudaFuncSetAttribute(dcn_offset_mma,
                         cudaFuncAttributeMaxDynamicSharedMemorySize, (int)smem1);
    dcn_offset_mma<<<dim3(Hn, Bn), 512, smem1>>>(inp, inter, offb);

    size_t smem2 = 1024 + 2 * 32768 + 18432 + 4608;   // 89,600 B
    cudaFuncSetAttribute(dcn_main_mma,
                         cudaFuncAttributeMaxDynamicSharedMemorySize, (int)smem2);
    dcn_main_mma<<<dim3(Hn, Bn), 512, smem2>>>(inp, bias, out);
}

// round 14
// speedup vs baseline: 1.6522x; 1.0157x over previous
#include <cuda_runtime.h>
#include <cuda_bf16.h>
#include <cuda_fp16.h>
#include <math.h>
#include <stdint.h>

#define Bn 4
#define Cn 128
#define Hn 128
#define Wn 128
#define On 128
#define Kn 9
#define KKn 1152          // Cn * Kn   (main GEMM K)
#define OKK 2304          // offset conv K: 256 ch * 9, kk = c*9+k

// scratch: sampling coordinates + modulation mask, [B][K][H][W]
__device__ float g_py[Bn * Kn * Hn * Wn];
__device__ float g_px[Bn * Kn * Hn * Wn];
__device__ float g_m [Bn * Kn * Hn * Wn];
// main weights, single fp16, [O][KK]
__device__ __half g_whi[On * KKn];
// offset-conv weights, fp16 hi + (lo * 1024), [32][OKK] (rows 27-31 zero)
__device__ __half g_owhi[32 * OKK];
__device__ __half g_owlo[32 * OKK];

#define SWZ(o) ((o) ^ (((o) >> 3) & 0x70))

__device__ __forceinline__ uint32_t smem_u32(const void* p) {
    uint32_t a;
    asm("{ .reg .u64 t; cvta.to.shared.u64 t, %1; cvt.u32.u64 %0, t; }"
        : "=r"(a) : "l"(p));
    return a;
}
__device__ __forceinline__ void ldsm4(uint32_t* r, uint32_t addr) {
    asm volatile("ldmatrix.sync.aligned.m8n8.x4.shared.b16 {%0,%1,%2,%3}, [%4];"
        : "=r"(r[0]), "=r"(r[1]), "=r"(r[2]), "=r"(r[3]) : "r"(addr));
}
__device__ __forceinline__ void mma_f16(float* d, const uint32_t* a,
                                        uint32_t b0, uint32_t b1) {
    asm volatile(
        "mma.sync.aligned.m16n8k16.row.col.f32.f16.f16.f32 "
        "{%0,%1,%2,%3}, {%4,%5,%6,%7}, {%8,%9}, {%0,%1,%2,%3};"
        : "+f"(d[0]), "+f"(d[1]), "+f"(d[2]), "+f"(d[3])
        : "r"(a[0]), "r"(a[1]), "r"(a[2]), "r"(a[3]), "r"(b0), "r"(b1));
}
__device__ __forceinline__ void cp16(uint32_t dst, const void* src) {
    asm volatile("cp.async.cg.shared.global [%0], [%1], 16;"
                 :: "r"(dst), "l"(src) : "memory");
}
#define CP_COMMIT() asm volatile("cp.async.commit_group;" ::: "memory")
#define CP_WAIT0()  asm volatile("cp.async.wait_group 0;" ::: "memory")
#define BAR_SYNC(id)   asm volatile("bar.sync %0, 512;"   :: "r"(id) : "memory")
#define BAR_ARRIVE(id) asm volatile("bar.arrive %0, 512;" :: "r"(id) : "memory")
#define MEMBAR_CTA()   asm volatile("membar.cta;" ::: "memory")

// packed fp16 pair
__device__ __forceinline__ uint32_t packh2(float v0, float v1) {
    uint32_t r;
    asm("cvt.rn.f16x2.f32 %0, %1, %2;" : "=r"(r) : "f"(v1), "f"(v0));
    return r;
}

// ---------------------------------------------------------------------------
// Kernel 0a/0b: weight prep
// ---------------------------------------------------------------------------
__global__ void dcn_wsplit_kernel(const float* __restrict__ wgt) {
    int i = blockIdx.x * 256 + threadIdx.x;
    if (i < On * KKn) g_whi[i] = __float2half(wgt[i]);
}
__global__ void dcn_owsplit_kernel(const float* __restrict__ offw) {
    int i = blockIdx.x * 256 + threadIdx.x;
    if (i >= 32 * OKK) return;
    int r = i / OKK;
    float w = (r < 27) ? offw[i] : 0.f;
    __half h = __float2half(w);
    g_owhi[i] = h;
    // residual scaled x1024 -> normal fp16 range (avoids subnormal operands)
    g_owlo[i] = __float2half((w - __half2float(h)) * 1024.f);
}

// ---------------------------------------------------------------------------
// Kernel 1: offset conv, interleaved fill+MMA (proven structure), fp16
// 2-term: D = Ah*B + (Al*B)/1024. One CTA per (b,y): 512 thr, warp tile
// 16o x 16px. per buffer (stride 24576): Ah +0 (4K), Al +4096 (4K), Bh +8192 (16K)
// ---------------------------------------------------------------------------
__global__ __launch_bounds__(512) void dcn_offset_mma(
    const float* __restrict__ inp,
    const float* __restrict__ inter,
    const float* __restrict__ offb)
{
    extern __shared__ char smem_raw[];
    char* tiles = (char*)(((uintptr_t)smem_raw + 1023) & ~(uintptr_t)1023);

    const int tid = threadIdx.x;
    const int wid = tid >> 5;
    const int lid = tid & 31;
    const int g   = lid >> 2;
    const int t   = lid & 3;
    const int y   = blockIdx.x;
    const int b   = blockIdx.y;
    const int m0  = (wid & 1) * 16;
    const int n0  = (wid >> 1) * 16;

    const int idx = lid >> 3, lr = lid & 7;
    const uint32_t aoffb = (uint32_t)((m0 + (idx & 1) * 8 + lr) * 128 + (idx >> 1) * 16);
    const uint32_t boffb = (uint32_t)((n0 + (idx >> 1) * 8 + lr) * 128 + (idx & 1) * 16);
    const uint32_t tbase = smem_u32(tiles);

    const int px0 = tid & 127;
    const int jg0 = tid >> 7;

    float acch[2][4], accl[2][4];
    #pragma unroll
    for (int j = 0; j < 2; j++)
        #pragma unroll
        for (int q = 0; q < 4; q++) { acch[j][q] = 0.f; accl[j][q] = 0.f; }

    auto bload = [&](int chunk, int jg, float* fv) {
        #pragma unroll
        for (int j = 0; j < 8; ++j) {
            int kk = chunk * 64 + jg * 8 + j;
            int c  = kk / 9;
            int k  = kk - c * 9;
            int ky = k / 3;
            int kx = k - ky * 3;
            int yg = y + ky - 1;
            int xg = px0 + kx - 1;
            float v = 0.f;
            if (yg >= 0 && yg < Hn && xg >= 0 && xg < Wn) {
                const float* base = (c < Cn)
                    ? inp   + ((size_t)b * Cn + c) * (Hn * Wn)
                    : inter + ((size_t)b * Cn + (c - Cn)) * (Hn * Wn);
                v = base[yg * Wn + xg];
            }
            fv[j] = v;
        }
    };
    auto bstore = [&](char* buf, int jg, const float* fv) {
        uint4 vh4;
        vh4.x = packh2(fv[0], fv[1]);
        vh4.y = packh2(fv[2], fv[3]);
        vh4.z = packh2(fv[4], fv[5]);
        vh4.w = packh2(fv[6], fv[7]);
        uint32_t off = (uint32_t)(px0 * 128 + jg * 16);
        *(uint4*)(buf + 8192 + SWZ(off)) = vh4;
    };
    auto mma_half = [&](uint32_t cu, int ks0) {
        uint32_t Ah = cu, Al = cu + 4096, Bh = cu + 8192;
        #pragma unroll
        for (int kq = 0; kq < 2; ++kq) {
            int ks = ks0 + kq;
            uint32_t ah[4], al[4], bh[4];
            uint32_t ao = SWZ(aoffb + ks * 32);
            uint32_t bo = SWZ(boffb + ks * 32);
            ldsm4(ah, Ah + ao);
            ldsm4(al, Al + ao);
            ldsm4(bh, Bh + bo);
            #pragma unroll
            for (int nt = 0; nt < 2; ++nt) {
                mma_f16(acch[nt], ah, bh[2*nt], bh[2*nt+1]);
                mma_f16(accl[nt], al, bh[2*nt], bh[2*nt+1]);
            }
        }
    };

    // prologue: synchronous fill of chunk 0
    {
        char* buf = tiles;
        {
            int i = tid;
            if (i < 512) {
                int tt = i >> 8;
                int r  = (i >> 3) & 31;
                int j  = i & 7;
                const char* src = (tt ? (const char*)g_owlo : (const char*)g_owhi)
                                  + r * (OKK * 2) + j * 16;
                *(uint4*)(buf + tt * 4096 + SWZ((uint32_t)(r * 128 + j * 16)))
                    = *(const uint4*)src;
            }
        }
        float fv[8];
        bload(0, jg0, fv);     bstore(buf, jg0, fv);
        bload(0, jg0 + 4, fv); bstore(buf, jg0 + 4, fv);
    }
    __syncthreads();

    for (int c = 0; c < 36; ++c) {
        uint32_t cu = tbase + (uint32_t)((c & 1) * 24576);
        char* nbuf  = tiles + (size_t)((c + 1) & 1) * 24576;
        uint32_t nb = tbase + (uint32_t)(((c + 1) & 1) * 24576);
        const bool pre = (c + 1 < 36);

        if (pre) {
            int i  = tid;
            int tt = i >> 8;
            int r  = (i >> 3) & 31;
            int j  = i & 7;
            const char* src = (tt ? (const char*)g_owlo : (const char*)g_owhi)
                              + r * (OKK * 2) + (c + 1) * 128 + j * 16;
            cp16(nb + tt * 4096 + SWZ((uint32_t)(r * 128 + j * 16)), src);
            CP_COMMIT();
        }

        float fv[8];
        if (pre) bload(c + 1, jg0, fv);
        mma_half(cu, 0);
        if (pre) bstore(nbuf, jg0, fv);

        if (pre) bload(c + 1, jg0 + 4, fv);
        mma_half(cu, 2);
        if (pre) bstore(nbuf, jg0 + 4, fv);

        if (pre) CP_WAIT0();
        __syncthreads();
    }

    // epilogue 1: fragments -> smem D[32][132] (+ bias); recombine lo/1024
    float* Dsm = (float*)tiles;
    {
        const float s = 1.f / 1024.f;
        int r0 = m0 + g;
        int r1 = r0 + 8;
        float bo0 = (r0 < 27) ? offb[r0] : 0.f;
        float bo1 = (r1 < 27) ? offb[r1] : 0.f;
        #pragma unroll
        for (int nt = 0; nt < 2; ++nt) {
            int cx = n0 + nt * 8 + 2 * t;
            Dsm[r0 * 132 + cx]     = acch[nt][0] + accl[nt][0] * s + bo0;
            Dsm[r0 * 132 + cx + 1] = acch[nt][1] + accl[nt][1] * s + bo0;
            Dsm[r1 * 132 + cx]     = acch[nt][2] + accl[nt][2] * s + bo1;
            Dsm[r1 * 132 + cx + 1] = acch[nt][3] + accl[nt][3] * s + bo1;
        }
    }
    __syncthreads();

    // epilogue 2: coordinate / mask transform
    if (tid < 128) {
        int x = tid;
        #pragma unroll
        for (int k = 0; k < 9; ++k) {
            float dy = Dsm[(2 * k) * 132 + x];
            float dx = Dsm[(2 * k + 1) * 132 + x];
            float mv = 1.f / (1.f + expf(-Dsm[(18 + k) * 132 + x]));
            int idx2 = ((b * Kn + k) * Hn + y) * Wn + x;
            g_py[idx2] = dy + (float)(y - 1 + (k / 3));
            g_px[idx2] = dx + (float)(x - 1 + (k % 3));
            g_m [idx2] = mv;
        }
    }
}

// ---------------------------------------------------------------------------
// Kernel 2: main GEMM, warp-specialized, single fp16, 3-stage pipeline.
// One CTA per (b,y): warps 0-7 consumers (tile 32o x 64px), warps 8-15
// producers. 3 buffers, stride 32768: A +0 (16K), B +16384. tables @98304.
// ---------------------------------------------------------------------------
__global__ __launch_bounds__(512) void dcn_main_mma(
    const float* __restrict__ inp,
    const float* __restrict__ bias,
    float* __restrict__ out)
{
    extern __shared__ char smem_raw[];
    char* tiles = (char*)(((uintptr_t)smem_raw + 1023) & ~(uintptr_t)1023);
    float4*   cwgt = (float4*)(tiles + 98304);            // [9*128]
    uint32_t* cpak = (uint32_t*)(tiles + 98304 + 18432);  // [9*128]

    const int tid = threadIdx.x;
    const int wid = tid >> 5;
    const int lid = tid & 31;
    const int y   = blockIdx.x;
    const int b   = blockIdx.y;
    const uint32_t tbase = smem_u32(tiles);
    const float* binp = inp + (size_t)b * Cn * Hn * Wn;

    // corner tables (all 512 threads)
    for (int e = tid; e < 1152; e += 512) {
        int k  = e >> 7;
        int px = e & 127;
        int gi = ((b * Kn + k) * Hn + y) * Wn + px;
        float pyv = g_py[gi];
        float pxv = g_px[gi];
        float mv  = g_m[gi];
        float y0f = floorf(pyv);
        float x0f = floorf(pxv);
        float wy = pyv - y0f;
        float wx = pxv - x0f;
        int yI = (int)y0f;
        int xI = (int)x0f;
        float vy0 = (yI >= 0  && yI <= Hn - 1) ? 1.f : 0.f;
        float vy1 = (yI >= -1 && yI <= Hn - 2) ? 1.f : 0.f;
        float vx0 = (xI >= 0  && xI <= Wn - 1) ? 1.f : 0.f;
        float vx1 = (xI >= -1 && xI <= Wn - 2) ? 1.f : 0.f;
        float w00 = (1.f - wy) * (1.f - wx) * mv * (vy0 * vx0);
        float w01 = (1.f - wy) * wx         * mv * (vy0 * vx1);
        float w10 = wy * (1.f - wx)         * mv * (vy1 * vx0);
        float w11 = wy * wx                 * mv * (vy1 * vx1);
        int y0c = min(max(yI, 0), Hn - 1);
        int y1c = min(max(yI + 1, 0), Hn - 1);
        int x0c = min(max(xI, 0), Wn - 1);
        int x1c = min(max(xI + 1, 0), Wn - 1);
        cwgt[e] = make_float4(w00, w01, w10, w11);
        cpak[e] = (uint32_t)(y0c * Wn + x0c)
                | ((uint32_t)(x1c - x0c) << 14)
                | ((uint32_t)(y1c - y0c) << 15);
    }
    __syncthreads();

    auto bload = [&](int chunk, int jg, int px0, float* cr) {
        #pragma unroll
        for (int j = 0; j < 8; ++j) {
            int kk = chunk * 64 + jg * 8 + j;
            int c9 = kk / 9;
            int k  = kk - c9 * 9;
            int e  = (k << 7) + px0;
            uint32_t p = cpak[e];
            int base = (int)(p & 0x3fff);
            int dxs  = (int)((p >> 14) & 1);
            int dyr  = ((int)((p >> 15) & 1)) << 7;
            const float* pl = binp + (c9 << 14);
            cr[4*j+0] = pl[base];
            cr[4*j+1] = pl[base + dxs];
            cr[4*j+2] = pl[base + dyr];
            cr[4*j+3] = pl[base + dyr + dxs];
        }
    };
    auto bstore = [&](char* bbuf, int chunk, int jg, int px0, const float* cr) {
        float v[8];
        #pragma unroll
        for (int j = 0; j < 8; ++j) {
            int kk = chunk * 64 + jg * 8 + j;
            int c9 = kk / 9;
            int k  = kk - c9 * 9;
            int e  = (k << 7) + px0;
            float4 w = cwgt[e];
            v[j] = w.x * cr[4*j+0] + w.y * cr[4*j+1]
                 + w.z * cr[4*j+2] + w.w * cr[4*j+3];
        }
        uint4 vh4;
        vh4.x = packh2(v[0], v[1]);
        vh4.y = packh2(v[2], v[3]);
        vh4.z = packh2(v[4], v[5]);
        vh4.w = packh2(v[6], v[7]);
        uint32_t off = (uint32_t)(px0 * 128 + jg * 16);
        *(uint4*)(bbuf + SWZ(off)) = vh4;
    };

    // prologue: all 512 threads fill buffer 0 (chunk 0)
    {
        char* A0 = tiles;
        char* B0 = tiles + 16384;
        #pragma unroll
        for (int i = tid; i < 1024; i += 512) {
            int r = i >> 3;
            int j = i & 7;
            const char* src = (const char*)g_whi + r * 2304 + j * 16;
            *(uint4*)(A0 + SWZ((uint32_t)(r * 128 + j * 16))) = *(const uint4*)src;
        }
        int px0 = tid & 127;
        int jb  = (tid >> 7) * 2;
        float cr[32];
        #pragma unroll
        for (int it = 0; it < 2; ++it) {
            bload(0, jb + it, px0, cr);
            bstore(B0, 0, jb + it, px0, cr);
        }
    }
    __syncthreads();

    if (wid < 8) {
        // ===================== CONSUMER =====================
        const int g  = lid >> 2;
        const int t  = lid & 3;
        const int m0 = (wid & 3) * 32;
        const int n0 = (wid >> 2) * 64;
        const int idx = lid >> 3, lr = lid & 7;
        const uint32_t aoff0 = (uint32_t)((m0 + (idx & 1) * 8 + lr) * 128 + (idx >> 1) * 16);
        const uint32_t aoff1 = aoff0 + 16 * 128;
        uint32_t boffq[4];
        #pragma unroll
        for (int q = 0; q < 4; ++q)
            boffq[q] = (uint32_t)((n0 + q * 16 + (idx >> 1) * 8 + lr) * 128 + (idx & 1) * 16);

        float acc[2][8][4];
        #pragma unroll
        for (int i = 0; i < 2; i++)
            #pragma unroll
            for (int j = 0; j < 8; j++)
                #pragma unroll
                for (int q = 0; q < 4; q++) acc[i][j][q] = 0.f;

        for (int c = 0; c < 18; ++c) {
            int s = c % 3;
            if (c) BAR_SYNC(1 + s);
            uint32_t bufb = tbase + (uint32_t)(s * 32768);
            uint32_t Ah = bufb, Bh = bufb + 16384;
            #pragma unroll
            for (int ks = 0; ks < 4; ++ks) {
                uint32_t ah[2][4];
                uint32_t a0 = SWZ(aoff0 + ks * 32);
                uint32_t a1 = SWZ(aoff1 + ks * 32);
                ldsm4(ah[0], Ah + a0); ldsm4(ah[1], Ah + a1);
                #pragma unroll
                for (int q = 0; q < 4; ++q) {
                    uint32_t bo = SWZ(boffq[q] + ks * 32);
                    uint32_t bh[4];
                    ldsm4(bh, Bh + bo);
                    #pragma unroll
                    for (int hf = 0; hf < 2; ++hf) {
                        int nt = q * 2 + hf;
                        uint32_t h0 = bh[2*hf], h1 = bh[2*hf+1];
                        #pragma unroll
                        for (int mt = 0; mt < 2; ++mt)
                            mma_f16(acc[mt][nt], ah[mt], h0, h1);
                    }
                }
            }
            BAR_ARRIVE(4 + s);
        }

        // epilogue: add bias, store float2 pairs
        #pragma unroll
        for (int mt = 0; mt < 2; ++mt) {
            int r0 = m0 + mt * 16 + g;
            int r1 = r0 + 8;
            float bo0 = bias[r0];
            float bo1 = bias[r1];
            float* row0 = out + (((size_t)b * On + r0) * Hn + y) * Wn;
            float* row1 = out + (((size_t)b * On + r1) * Hn + y) * Wn;
            #pragma unroll
            for (int nt = 0; nt < 8; ++nt) {
                int cx = n0 + nt * 8 + 2 * t;
                float2 v0 = make_float2(acc[mt][nt][0] + bo0, acc[mt][nt][1] + bo0);
                float2 v1 = make_float2(acc[mt][nt][2] + bo1, acc[mt][nt][3] + bo1);
                *(float2*)(row0 + cx) = v0;
                *(float2*)(row1 + cx) = v1;
            }
        }
    } else {
        // ===================== PRODUCER =====================
        const int ptid = tid - 256;
        const int px0  = ptid & 127;
        const int jb   = (ptid >> 7) * 4;
        for (int cn = 1; cn < 18; ++cn) {
            int s = cn % 3;
            if (cn >= 3) BAR_SYNC(4 + s);
            char* Abuf = tiles + (size_t)s * 32768;
            char* Bbuf = tiles + 16384 + (size_t)s * 32768;
            // A via cp.async: 4 x 16B per thread
            #pragma unroll
            for (int i = ptid; i < 1024; i += 256) {
                int r = i >> 3;
                int j = i & 7;
                const char* src = (const char*)g_whi + r * 2304 + cn * 128 + j * 16;
                cp16(smem_u32(Abuf) + SWZ((uint32_t)(r * 128 + j * 16)), src);
            }
            CP_COMMIT();
            // B: 4 items, 2-deep pipelined gather
            float cr[2][32];
            bload(cn, jb, px0, cr[0]);
            #pragma unroll
            for (int it = 0; it < 4; ++it) {
                if (it < 3) bload(cn, jb + it + 1, px0, cr[(it + 1) & 1]);
                bstore(Bbuf, cn, jb + it, px0, cr[it & 1]);
            }
            CP_WAIT0();
            MEMBAR_CTA();
            BAR_ARRIVE(1 + s);
        }
    }
}

// ---------------------------------------------------------------------------
extern "C" void kernel_launch(void* const* d_in, const int* in_sizes, int n_in,
                              void* d_out, int out_size)
{
    const float* inp   = (const float*)d_in[0];
    const float* inter = (const float*)d_in[1];
    const float* offw  = (const float*)d_in[2];
    const float* offb  = (const float*)d_in[3];
    const float* wgt   = (const float*)d_in[4];
    const float* bias  = (const float*)d_in[5];
    float* out = (float*)d_out;

    dcn_wsplit_kernel<<<(On * KKn + 255) / 256, 256>>>(wgt);
    dcn_owsplit_kernel<<<(32 * OKK + 255) / 256, 256>>>(offw);

    size_t smem1 = 1024 + 2 * 24576;   // 50,176 B
    cudaFuncSetAttribute(dcn_offset_mma,
                         cudaFuncAttributeMaxDynamicSharedMemorySize, (int)smem1);
    dcn_offset_mma<<<dim3(Hn, Bn), 512, smem1>>>(inp, inter, offb);

    size_t smem2 = 1024 + 3 * 32768 + 18432 + 4608;   // 122,368 B
    cudaFuncSetAttribute(dcn_main_mma,
                         cudaFuncAttributeMaxDynamicSharedMemorySize, (int)smem2);
    dcn_main_mma<<<dim3(Hn, Bn), 512, smem2>>>(inp, bias, out);
}

// round 15
// speedup vs baseline: 1.7534x; 1.0613x over previous
#include <cuda_runtime.h>
#include <cuda_bf16.h>
#include <cuda_fp16.h>
#include <math.h>
#include <stdint.h>

#define Bn 4
#define Cn 128
#define Hn 128
#define Wn 128
#define On 128
#define Kn 9
#define KKn 1152          // Cn * Kn   (main GEMM K)
#define OKK 2304          // offset conv K: 256 ch * 9, kk = c*9+k

// scratch: sampling coordinates + modulation mask, [B][K][H][W]
__device__ float g_py[Bn * Kn * Hn * Wn];
__device__ float g_px[Bn * Kn * Hn * Wn];
__device__ float g_m [Bn * Kn * Hn * Wn];
// main weights, single fp16, [O][KK]
__device__ __half g_whi[On * KKn];
// offset-conv weights, fp16 hi + (lo * 1024), [32][OKK] (rows 27-31 zero)
__device__ __half g_owhi[32 * OKK];
__device__ __half g_owlo[32 * OKK];

#define SWZ(o) ((o) ^ (((o) >> 3) & 0x70))

__device__ __forceinline__ uint32_t smem_u32(const void* p) {
    uint32_t a;
    asm("{ .reg .u64 t; cvta.to.shared.u64 t, %1; cvt.u32.u64 %0, t; }"
        : "=r"(a) : "l"(p));
    return a;
}
__device__ __forceinline__ void ldsm4(uint32_t* r, uint32_t addr) {
    asm volatile("ldmatrix.sync.aligned.m8n8.x4.shared.b16 {%0,%1,%2,%3}, [%4];"
        : "=r"(r[0]), "=r"(r[1]), "=r"(r[2]), "=r"(r[3]) : "r"(addr));
}
__device__ __forceinline__ void mma_f16(float* d, const uint32_t* a,
                                        uint32_t b0, uint32_t b1) {
    asm volatile(
        "mma.sync.aligned.m16n8k16.row.col.f32.f16.f16.f32 "
        "{%0,%1,%2,%3}, {%4,%5,%6,%7}, {%8,%9}, {%0,%1,%2,%3};"
        : "+f"(d[0]), "+f"(d[1]), "+f"(d[2]), "+f"(d[3])
        : "r"(a[0]), "r"(a[1]), "r"(a[2]), "r"(a[3]), "r"(b0), "r"(b1));
}
__device__ __forceinline__ void cp16(uint32_t dst, const void* src) {
    asm volatile("cp.async.cg.shared.global [%0], [%1], 16;"
                 :: "r"(dst), "l"(src) : "memory");
}
#define CP_COMMIT() asm volatile("cp.async.commit_group;" ::: "memory")
#define CP_WAIT0()  asm volatile("cp.async.wait_group 0;" ::: "memory")
#define BAR_SYNC(id)   asm volatile("bar.sync %0, 512;"   :: "r"(id) : "memory")
#define BAR_ARRIVE(id) asm volatile("bar.arrive %0, 512;" :: "r"(id) : "memory")
#define MEMBAR_CTA()   asm volatile("membar.cta;" ::: "memory")

// packed fp16 pair
__device__ __forceinline__ uint32_t packh2(float v0, float v1) {
    uint32_t r;
    asm("cvt.rn.f16x2.f32 %0, %1, %2;" : "=r"(r) : "f"(v1), "f"(v0));
    return r;
}

// ---------------------------------------------------------------------------
// Kernel 0a/0b: weight prep
// ---------------------------------------------------------------------------
__global__ void dcn_wsplit_kernel(const float* __restrict__ wgt) {
    int i = blockIdx.x * 256 + threadIdx.x;
    if (i < On * KKn) g_whi[i] = __float2half(wgt[i]);
}
__global__ void dcn_owsplit_kernel(const float* __restrict__ offw) {
    int i = blockIdx.x * 256 + threadIdx.x;
    if (i >= 32 * OKK) return;
    int r = i / OKK;
    float w = (r < 27) ? offw[i] : 0.f;
    __half h = __float2half(w);
    g_owhi[i] = h;
    g_owlo[i] = __float2half((w - __half2float(h)) * 1024.f);
}

// ---------------------------------------------------------------------------
// Kernel 1 (unchanged R14): offset conv, interleaved fill+MMA, fp16 2-term
// (scaled-lo A, single-fp16 B). One CTA per (b,y): 512 thr, tile 16o x 16px.
// per buffer (stride 24576): Ah +0 (4K), Al +4096 (4K), Bh +8192 (16K)
// ---------------------------------------------------------------------------
__global__ __launch_bounds__(512) void dcn_offset_mma(
    const float* __restrict__ inp,
    const float* __restrict__ inter,
    const float* __restrict__ offb)
{
    extern __shared__ char smem_raw[];
    char* tiles = (char*)(((uintptr_t)smem_raw + 1023) & ~(uintptr_t)1023);

    const int tid = threadIdx.x;
    const int wid = tid >> 5;
    const int lid = tid & 31;
    const int g   = lid >> 2;
    const int t   = lid & 3;
    const int y   = blockIdx.x;
    const int b   = blockIdx.y;
    const int m0  = (wid & 1) * 16;
    const int n0  = (wid >> 1) * 16;

    const int idx = lid >> 3, lr = lid & 7;
    const uint32_t aoffb = (uint32_t)((m0 + (idx & 1) * 8 + lr) * 128 + (idx >> 1) * 16);
    const uint32_t boffb = (uint32_t)((n0 + (idx >> 1) * 8 + lr) * 128 + (idx & 1) * 16);
    const uint32_t tbase = smem_u32(tiles);

    const int px0 = tid & 127;
    const int jg0 = tid >> 7;

    float acch[2][4], accl[2][4];
    #pragma unroll
    for (int j = 0; j < 2; j++)
        #pragma unroll
        for (int q = 0; q < 4; q++) { acch[j][q] = 0.f; accl[j][q] = 0.f; }

    auto bload = [&](int chunk, int jg, float* fv) {
        int kk0 = chunk * 64 + jg * 8;
        int c   = kk0 / 9;
        int k   = kk0 - c * 9;
        #pragma unroll
        for (int j = 0; j < 8; ++j) {
            int ky = k / 3;
            int kx = k - ky * 3;
            int yg = y + ky - 1;
            int xg = px0 + kx - 1;
            float v = 0.f;
            if (yg >= 0 && yg < Hn && xg >= 0 && xg < Wn) {
                const float* base = (c < Cn)
                    ? inp   + ((size_t)b * Cn + c) * (Hn * Wn)
                    : inter + ((size_t)b * Cn + (c - Cn)) * (Hn * Wn);
                v = base[yg * Wn + xg];
            }
            fv[j] = v;
            if (++k == 9) { k = 0; ++c; }
        }
    };
    auto bstore = [&](char* buf, int jg, const float* fv) {
        uint4 vh4;
        vh4.x = packh2(fv[0], fv[1]);
        vh4.y = packh2(fv[2], fv[3]);
        vh4.z = packh2(fv[4], fv[5]);
        vh4.w = packh2(fv[6], fv[7]);
        uint32_t off = (uint32_t)(px0 * 128 + jg * 16);
        *(uint4*)(buf + 8192 + SWZ(off)) = vh4;
    };
    auto mma_half = [&](uint32_t cu, int ks0) {
        uint32_t Ah = cu, Al = cu + 4096, Bh = cu + 8192;
        #pragma unroll
        for (int kq = 0; kq < 2; ++kq) {
            int ks = ks0 + kq;
            uint32_t ah[4], al[4], bh[4];
            uint32_t ao = SWZ(aoffb + ks * 32);
            uint32_t bo = SWZ(boffb + ks * 32);
            ldsm4(ah, Ah + ao);
            ldsm4(al, Al + ao);
            ldsm4(bh, Bh + bo);
            #pragma unroll
            for (int nt = 0; nt < 2; ++nt) {
                mma_f16(acch[nt], ah, bh[2*nt], bh[2*nt+1]);
                mma_f16(accl[nt], al, bh[2*nt], bh[2*nt+1]);
            }
        }
    };

    // prologue: synchronous fill of chunk 0
    {
        char* buf = tiles;
        {
            int i = tid;
            if (i < 512) {
                int tt = i >> 8;
                int r  = (i >> 3) & 31;
                int j  = i & 7;
                const char* src = (tt ? (const char*)g_owlo : (const char*)g_owhi)
                                  + r * (OKK * 2) + j * 16;
                *(uint4*)(buf + tt * 4096 + SWZ((uint32_t)(r * 128 + j * 16)))
                    = *(const uint4*)src;
            }
        }
        float fv[8];
        bload(0, jg0, fv);     bstore(buf, jg0, fv);
        bload(0, jg0 + 4, fv); bstore(buf, jg0 + 4, fv);
    }
    __syncthreads();

    for (int c = 0; c < 36; ++c) {
        uint32_t cu = tbase + (uint32_t)((c & 1) * 24576);
        char* nbuf  = tiles + (size_t)((c + 1) & 1) * 24576;
        uint32_t nb = tbase + (uint32_t)(((c + 1) & 1) * 24576);
        const bool pre = (c + 1 < 36);

        if (pre) {
            int i  = tid;
            int tt = i >> 8;
            int r  = (i >> 3) & 31;
            int j  = i & 7;
            const char* src = (tt ? (const char*)g_owlo : (const char*)g_owhi)
                              + r * (OKK * 2) + (c + 1) * 128 + j * 16;
            cp16(nb + tt * 4096 + SWZ((uint32_t)(r * 128 + j * 16)), src);
            CP_COMMIT();
        }

        float fv[8];
        if (pre) bload(c + 1, jg0, fv);
        mma_half(cu, 0);
        if (pre) bstore(nbuf, jg0, fv);

        if (pre) bload(c + 1, jg0 + 4, fv);
        mma_half(cu, 2);
        if (pre) bstore(nbuf, jg0 + 4, fv);

        if (pre) CP_WAIT0();
        __syncthreads();
    }

    // epilogue 1: fragments -> smem D[32][132] (+ bias); recombine lo/1024
    float* Dsm = (float*)tiles;
    {
        const float s = 1.f / 1024.f;
        int r0 = m0 + g;
        int r1 = r0 + 8;
        float bo0 = (r0 < 27) ? offb[r0] : 0.f;
        float bo1 = (r1 < 27) ? offb[r1] : 0.f;
        #pragma unroll
        for (int nt = 0; nt < 2; ++nt) {
            int cx = n0 + nt * 8 + 2 * t;
            Dsm[r0 * 132 + cx]     = acch[nt][0] + accl[nt][0] * s + bo0;
            Dsm[r0 * 132 + cx + 1] = acch[nt][1] + accl[nt][1] * s + bo0;
            Dsm[r1 * 132 + cx]     = acch[nt][2] + accl[nt][2] * s + bo1;
            Dsm[r1 * 132 + cx + 1] = acch[nt][3] + accl[nt][3] * s + bo1;
        }
    }
    __syncthreads();

    // epilogue 2: coordinate / mask transform
    if (tid < 128) {
        int x = tid;
        #pragma unroll
        for (int k = 0; k < 9; ++k) {
            float dy = Dsm[(2 * k) * 132 + x];
            float dx = Dsm[(2 * k + 1) * 132 + x];
            float mv = 1.f / (1.f + expf(-Dsm[(18 + k) * 132 + x]));
            int idx2 = ((b * Kn + k) * Hn + y) * Wn + x;
            g_py[idx2] = dy + (float)(y - 1 + (k / 3));
            g_px[idx2] = dx + (float)(x - 1 + (k % 3));
            g_m [idx2] = mv;
        }
    }
}

// ---------------------------------------------------------------------------
// Kernel 2: main GEMM, warp-specialized, single fp16, 2 chunks per barrier
// epoch (9 epochs). One CTA per (b,y): warps 0-7 consumers (tile 32o x 64px),
// warps 8-15 producers. Buffer stride 65536 holds a chunk PAIR:
// sub s2 at +s2*32768 {A +0 (16K), B +16384 (16K)}. tables @131072.
// ---------------------------------------------------------------------------
__global__ __launch_bounds__(512) void dcn_main_mma(
    const float* __restrict__ inp,
    const float* __restrict__ bias,
    float* __restrict__ out)
{
    extern __shared__ char smem_raw[];
    char* tiles = (char*)(((uintptr_t)smem_raw + 1023) & ~(uintptr_t)1023);
    float4*   cwgt = (float4*)(tiles + 131072);            // [9*128]
    uint32_t* cpak = (uint32_t*)(tiles + 131072 + 18432);  // [9*128]

    const int tid = threadIdx.x;
    const int wid = tid >> 5;
    const int lid = tid & 31;
    const int y   = blockIdx.x;
    const int b   = blockIdx.y;
    const uint32_t tbase = smem_u32(tiles);
    const float* binp = inp + (size_t)b * Cn * Hn * Wn;

    // corner tables (all 512 threads)
    for (int e = tid; e < 1152; e += 512) {
        int k  = e >> 7;
        int px = e & 127;
        int gi = ((b * Kn + k) * Hn + y) * Wn + px;
        float pyv = g_py[gi];
        float pxv = g_px[gi];
        float mv  = g_m[gi];
        float y0f = floorf(pyv);
        float x0f = floorf(pxv);
        float wy = pyv - y0f;
        float wx = pxv - x0f;
        int yI = (int)y0f;
        int xI = (int)x0f;
        float vy0 = (yI >= 0  && yI <= Hn - 1) ? 1.f : 0.f;
        float vy1 = (yI >= -1 && yI <= Hn - 2) ? 1.f : 0.f;
        float vx0 = (xI >= 0  && xI <= Wn - 1) ? 1.f : 0.f;
        float vx1 = (xI >= -1 && xI <= Wn - 2) ? 1.f : 0.f;
        float w00 = (1.f - wy) * (1.f - wx) * mv * (vy0 * vx0);
        float w01 = (1.f - wy) * wx         * mv * (vy0 * vx1);
        float w10 = wy * (1.f - wx)         * mv * (vy1 * vx0);
        float w11 = wy * wx                 * mv * (vy1 * vx1);
        int y0c = min(max(yI, 0), Hn - 1);
        int y1c = min(max(yI + 1, 0), Hn - 1);
        int x0c = min(max(xI, 0), Wn - 1);
        int x1c = min(max(xI + 1, 0), Wn - 1);
        cwgt[e] = make_float4(w00, w01, w10, w11);
        cpak[e] = (uint32_t)(y0c * Wn + x0c)
                | ((uint32_t)(x1c - x0c) << 14)
                | ((uint32_t)(y1c - y0c) << 15);
    }
    __syncthreads();

    auto bload = [&](int chunk, int jg, int px0, float* cr) {
        int kk0 = chunk * 64 + jg * 8;
        int c9  = kk0 / 9;
        int k   = kk0 - c9 * 9;
        #pragma unroll
        for (int j = 0; j < 8; ++j) {
            int e = (k << 7) + px0;
            uint32_t p = cpak[e];
            int base = (int)(p & 0x3fff);
            int dxs  = (int)((p >> 14) & 1);
            int dyr  = ((int)((p >> 15) & 1)) << 7;
            const float* pl = binp + (c9 << 14);
            cr[4*j+0] = pl[base];
            cr[4*j+1] = pl[base + dxs];
            cr[4*j+2] = pl[base + dyr];
            cr[4*j+3] = pl[base + dyr + dxs];
            if (++k == 9) { k = 0; ++c9; }
        }
    };
    auto bstore = [&](char* bbuf, int chunk, int jg, int px0, const float* cr) {
        int kk0 = chunk * 64 + jg * 8;
        int c9  = kk0 / 9;
        int k   = kk0 - c9 * 9;
        float v[8];
        #pragma unroll
        for (int j = 0; j < 8; ++j) {
            int e = (k << 7) + px0;
            float4 w = cwgt[e];
            v[j] = w.x * cr[4*j+0] + w.y * cr[4*j+1]
                 + w.z * cr[4*j+2] + w.w * cr[4*j+3];
            if (++k == 9) { k = 0; ++c9; }
        }
        uint4 vh4;
        vh4.x = packh2(v[0], v[1]);
        vh4.y = packh2(v[2], v[3]);
        vh4.z = packh2(v[4], v[5]);
        vh4.w = packh2(v[6], v[7]);
        uint32_t off = (uint32_t)(px0 * 128 + jg * 16);
        *(uint4*)(bbuf + SWZ(off)) = vh4;
    };

    // prologue: all 512 threads fill buffer 0 (chunks 0 and 1)
    {
        #pragma unroll
        for (int s2 = 0; s2 < 2; ++s2) {
            char* A0 = tiles + s2 * 32768;
            char* B0 = A0 + 16384;
            #pragma unroll
            for (int i = tid; i < 1024; i += 512) {
                int r = i >> 3;
                int j = i & 7;
                const char* src = (const char*)g_whi + r * 2304 + s2 * 128 + j * 16;
                *(uint4*)(A0 + SWZ((uint32_t)(r * 128 + j * 16))) = *(const uint4*)src;
            }
            int px0 = tid & 127;
            int jb  = (tid >> 7) * 2;
            float cr[32];
            #pragma unroll
            for (int it = 0; it < 2; ++it) {
                bload(s2, jb + it, px0, cr);
                bstore(B0, s2, jb + it, px0, cr);
            }
        }
    }
    __syncthreads();

    if (wid < 8) {
        // ===================== CONSUMER =====================
        const int g  = lid >> 2;
        const int t  = lid & 3;
        const int m0 = (wid & 3) * 32;
        const int n0 = (wid >> 2) * 64;
        const int idx = lid >> 3, lr = lid & 7;
        const uint32_t aoff0 = (uint32_t)((m0 + (idx & 1) * 8 + lr) * 128 + (idx >> 1) * 16);
        const uint32_t aoff1 = aoff0 + 16 * 128;
        uint32_t boffq[4];
        #pragma unroll
        for (int q = 0; q < 4; ++q)
            boffq[q] = (uint32_t)((n0 + q * 16 + (idx >> 1) * 8 + lr) * 128 + (idx & 1) * 16);

        float acc[2][8][4];
        #pragma unroll
        for (int i = 0; i < 2; i++)
            #pragma unroll
            for (int j = 0; j < 8; j++)
                #pragma unroll
                for (int q = 0; q < 4; q++) acc[i][j][q] = 0.f;

        for (int ep = 0; ep < 9; ++ep) {
            int s = ep & 1;
            if (ep) BAR_SYNC(1 + s);
            #pragma unroll
            for (int s2 = 0; s2 < 2; ++s2) {
                uint32_t bufb = tbase + (uint32_t)(s * 65536 + s2 * 32768);
                uint32_t Ah = bufb, Bh = bufb + 16384;
                #pragma unroll
                for (int ks = 0; ks < 4; ++ks) {
                    uint32_t ah[2][4];
                    uint32_t a0 = SWZ(aoff0 + ks * 32);
                    uint32_t a1 = SWZ(aoff1 + ks * 32);
                    ldsm4(ah[0], Ah + a0); ldsm4(ah[1], Ah + a1);
                    #pragma unroll
                    for (int q = 0; q < 4; ++q) {
                        uint32_t bo = SWZ(boffq[q] + ks * 32);
                        uint32_t bh[4];
                        ldsm4(bh, Bh + bo);
                        #pragma unroll
                        for (int hf = 0; hf < 2; ++hf) {
                            int nt = q * 2 + hf;
                            uint32_t h0 = bh[2*hf], h1 = bh[2*hf+1];
                            #pragma unroll
                            for (int mt = 0; mt < 2; ++mt)
                                mma_f16(acc[mt][nt], ah[mt], h0, h1);
                        }
                    }
                }
            }
            BAR_ARRIVE(3 + s);
        }

        // epilogue: add bias, store float2 pairs
        #pragma unroll
        for (int mt = 0; mt < 2; ++mt) {
            int r0 = m0 + mt * 16 + g;
            int r1 = r0 + 8;
            float bo0 = bias[r0];
            float bo1 = bias[r1];
            float* row0 = out + (((size_t)b * On + r0) * Hn + y) * Wn;
            float* row1 = out + (((size_t)b * On + r1) * Hn + y) * Wn;
            #pragma unroll
            for (int nt = 0; nt < 8; ++nt) {
                int cx = n0 + nt * 8 + 2 * t;
                float2 v0 = make_float2(acc[mt][nt][0] + bo0, acc[mt][nt][1] + bo0);
                float2 v1 = make_float2(acc[mt][nt][2] + bo1, acc[mt][nt][3] + bo1);
                *(float2*)(row0 + cx) = v0;
                *(float2*)(row1 + cx) = v1;
            }
        }
    } else {
        // ===================== PRODUCER =====================
        const int ptid = tid - 256;
        const int px0  = ptid & 127;
        const int jb   = (ptid >> 7) * 4;
        for (int en = 1; en < 9; ++en) {
            int s = en & 1;
            if (en >= 2) BAR_SYNC(3 + s);
            #pragma unroll
            for (int s2 = 0; s2 < 2; ++s2) {
                int chunk = 2 * en + s2;
                char* Abuf = tiles + (size_t)s * 65536 + (size_t)s2 * 32768;
                char* Bbuf = Abuf + 16384;
                // A via cp.async: 4 x 16B per thread
                #pragma unroll
                for (int i = ptid; i < 1024; i += 256) {
                    int r = i >> 3;
                    int j = i & 7;
                    const char* src = (const char*)g_whi + r * 2304 + chunk * 128 + j * 16;
                    cp16(smem_u32(Abuf) + SWZ((uint32_t)(r * 128 + j * 16)), src);
                }
                CP_COMMIT();
                // B: 4 items, 2-deep pipelined gather
                float cr[2][32];
                bload(chunk, jb, px0, cr[0]);
                #pragma unroll
                for (int it = 0; it < 4; ++it) {
                    if (it < 3) bload(chunk, jb + it + 1, px0, cr[(it + 1) & 1]);
                    bstore(Bbuf, chunk, jb + it, px0, cr[it & 1]);
                }
            }
            CP_WAIT0();
            MEMBAR_CTA();
            BAR_ARRIVE(1 + s);
        }
    }
}

// ---------------------------------------------------------------------------
extern "C" void kernel_launch(void* const* d_in, const int* in_sizes, int n_in,
                              void* d_out, int out_size)
{
    const float* inp   = (const float*)d_in[0];
    const float* inter = (const float*)d_in[1];
    const float* offw  = (const float*)d_in[2];
    const float* offb  = (const float*)d_in[3];
    const float* wgt   = (const float*)d_in[4];
    const float* bias  = (const float*)d_in[5];
    float* out = (float*)d_out;

    dcn_wsplit_kernel<<<(On * KKn + 255) / 256, 256>>>(wgt);
    dcn_owsplit_kernel<<<(32 * OKK + 255) / 256, 256>>>(offw);

    size_t smem1 = 1024 + 2 * 24576;   // 50,176 B
    cudaFuncSetAttribute(dcn_offset_mma,
                         cudaFuncAttributeMaxDynamicSharedMemorySize, (int)smem1);
    dcn_offset_mma<<<dim3(Hn, Bn), 512, smem1>>>(inp, inter, offb);

    size_t smem2 = 1024 + 2 * 65536 + 18432 + 4608;   // 155,136 B
    cudaFuncSetAttribute(dcn_main_mma,
                         cudaFuncAttributeMaxDynamicSharedMemorySize, (int)smem2);
    dcn_main_mma<<<dim3(Hn, Bn), 512, smem2>>>(inp, bias, out);
}